// round 16
// baseline (speedup 1.0000x reference)
#include <cuda_runtime.h>
#include <cuda_fp16.h>
#include <math.h>
#include <stdint.h>

#define HID  1024
#define H3   3072
#define VOC  3863
#define VOCP 3968
#define PON  514
#define PONP 640
#define TIN  64
#define TOUT 90
#define KP2  2048
#define KPE2 640
#define KS_ENC 4
#define KS_DEC 4
#define DEPTH 4
#define ASTG 16384
#define WSTG 12288
#define SK_E 8
#define SK_D 8
#define SMTOT   (DEPTH*(ASTG+WSTG))       // 114688 (bulk + enc: 2 CTAs/SM)
#define SMTOT_D (DEPTH*ASTG + SK_D*WSTG)  // 163840 (dec: A ring + resident W)

// ------------------------- device-global scratch ---------------------------
__device__ __half g_WhhI[3][H3*KP2];       // interleaved rows, K' = [hi|hi]
__device__ __half g_WihIe[2][H3*KPE2];
__device__ __half g_WihId[H3*KP2];
__device__ __half g_Wfc[576*KP2];
__device__ __half g_embE[VOCP*KPE2];       // K' = [hi|lo] (A exact)
__device__ __half g_embD[PONP*KP2];
__device__ float g_Ue[2][(size_t)VOCP*H3]; // input-gate tables (interleaved cols)
__device__ float g_Ud[(size_t)PONP*H3];
__device__ float g_bihE[2][H3];
__device__ float g_bihD[H3];
__device__ float g_bhhI[3][H3];
__device__ __half g_hAe[2][2][128*KP2];    // encoder h split A, ping-pong
__device__ float g_hFe[2][2][128*HID];
__device__ float g_hFd[2][128*HID];
__device__ float g_d0F[128*HID];
__device__ __half g_d0A[128*KP2];
__device__ __half g_fcA[(size_t)TOUT*128*KP2];  // decoder states (split) = FC input
__device__ float g_part[2][4][32][128*96]; // [z][ks][nx][m*96+n]
__device__ int   g_barE[2], g_barD;        // grid barriers (monotonic)

// ------------------------------ asm helpers --------------------------------
__device__ __forceinline__ uint32_t smem_u32(const void* p){
    uint32_t a;
    asm("{ .reg .u64 t; cvta.to.shared.u64 t, %1; cvt.u32.u64 %0, t; }":"=r"(a):"l"(p));
    return a;
}
__device__ __forceinline__ float tanh_fast(float x){
    float r;
    asm("tanh.approx.f32 %0, %1;" : "=f"(r) : "f"(x));
    return r;
}
__device__ __forceinline__ float sigmoid_fast(float x){
    return 0.5f*tanh_fast(0.5f*x) + 0.5f;
}
#define SWZ(x) ((x) ^ (((x) >> 3) & 0x70))
#define CP16(d_, s_) asm volatile("cp.async.cg.shared.global [%0], [%1], 16;"::"r"(d_),"l"(s_))
#define CPCOMMIT()   asm volatile("cp.async.commit_group;":::"memory")
#define CPWAIT(n)    asm volatile("cp.async.wait_group %0;"::"n"(n):"memory")
#define LDSM4(r, a) \
    asm volatile("ldmatrix.sync.aligned.m8n8.x4.shared.b16 {%0,%1,%2,%3}, [%4];" \
        : "=r"((r)[0]),"=r"((r)[1]),"=r"((r)[2]),"=r"((r)[3]) : "r"(a))
#define LDSM2(r, a) \
    asm volatile("ldmatrix.sync.aligned.m8n8.x2.shared.b16 {%0,%1}, [%2];" \
        : "=r"((r)[0]),"=r"((r)[1]) : "r"(a))
#define MMA16816(d, a, b) \
    asm volatile("mma.sync.aligned.m16n8k16.row.col.f32.f16.f16.f32 " \
        "{%0,%1,%2,%3}, {%4,%5,%6,%7}, {%8,%9}, {%0,%1,%2,%3};" \
        : "+f"((d)[0]),"+f"((d)[1]),"+f"((d)[2]),"+f"((d)[3]) \
        : "r"((a)[0]),"r"((a)[1]),"r"((a)[2]),"r"((a)[3]),"r"((b)[0]),"r"((b)[1]))

// grid-wide barrier: monotonic counter, fence + add + volatile spin
__device__ __forceinline__ void bar_sync(int* bar, int target)
{
    __threadfence();
    __syncthreads();
    if (threadIdx.x == 0){
        atomicAdd(bar, 1);
        while (*(volatile int*)bar < target)
            asm volatile("nanosleep.u32 32;");
        __threadfence();
    }
    __syncthreads();
}

// ------------------------------ prep kernels -------------------------------
// W: fp16 hi duplicated in both K' segments (W rounded once; A side exact).
__global__ void prep_w(const float* s0,const float* b0,const float* s1,const float* b1,
                       const float* s2,const float* b2,const float* s3,const float* b3,
                       const float* s4,const float* b4,const float* s5,const float* b5,
                       const float* s6)
{
    int which = blockIdx.y;
    const float* src; const float* bs = nullptr;
    __half* dst; float* bd = nullptr;
    int Nrows=H3, realR=H3, K=HID, Kpad=HID, inter=1;
    switch(which){
        case 0: src=s0; bs=b0; dst=g_WihIe[0]; bd=g_bihE[0]; K=300; Kpad=320; break;
        case 1: src=s1; bs=b1; dst=g_WihIe[1]; bd=g_bihE[1]; K=300; Kpad=320; break;
        case 2: src=s2; bs=b2; dst=g_WihId;    bd=g_bihD;    break;
        case 3: src=s3; bs=b3; dst=g_WhhI[0];  bd=g_bhhI[0]; break;
        case 4: src=s4; bs=b4; dst=g_WhhI[1];  bd=g_bhhI[1]; break;
        case 5: src=s5; bs=b5; dst=g_WhhI[2];  bd=g_bhhI[2]; break;
        default: src=s6; dst=g_Wfc; Nrows=576; realR=PON; inter=0; break;
    }
    int KP = 2*Kpad;
    long total = (long)Nrows*KP;
    for (long o=(long)blockIdx.x*blockDim.x+threadIdx.x; o<total;
         o += (long)gridDim.x*blockDim.x){
        int nr=(int)(o/KP), kq=(int)(o%KP), kk=kq%Kpad;
        int gr;
        if (inter){ int x=nr/96, rem=nr%96, g=rem/32, u=rem%32; gr=g*HID + x*32 + u; }
        else gr = nr;
        float v = (kk<K && gr<realR) ? src[(size_t)gr*K+kk] : 0.f;
        dst[o] = __float2half(v);
        if (kq==0 && bd) bd[nr] = (gr<realR) ? bs[gr] : 0.f;
    }
}
// Embedding split: [hi | lo] (A exact across the two terms)
__global__ void prep_a(const float* srcE, const float* srcD)
{
    int which = blockIdx.y;
    const float* src; __half* dst; int R, realR, K, Kpad;
    if (which==0){ src=srcE; dst=g_embE; R=VOCP; realR=VOC; K=300; Kpad=320; }
    else         { src=srcD; dst=g_embD; R=PONP; realR=PON; K=HID; Kpad=HID; }
    int KP = 2*Kpad;
    long total = (long)R*KP;
    for (long o=(long)blockIdx.x*blockDim.x+threadIdx.x; o<total;
         o += (long)gridDim.x*blockDim.x){
        int r=(int)(o/KP), kq=(int)(o%KP), seg=kq/Kpad, kk=kq%Kpad;
        int gr = r<realR ? r : 0;
        float v = kk<K ? src[(size_t)gr*K+kk] : 0.f;
        __half hi = __float2half(v);
        dst[o] = (seg==1) ? __float2half(v - __half2float(hi)) : hi;
    }
}
__global__ void init_h(){
    int i = blockIdx.x*blockDim.x+threadIdx.x;
    if (i < 128*HID){ g_hFe[0][0][i]=0.f; g_hFe[1][0][i]=0.f; }
    if (i < 128*KP2){
        g_hAe[0][0][i]=__float2half(0.f);
        g_hAe[1][0][i]=__float2half(0.f);
    }
    if (i == 0){ g_barE[0] = 0; g_barE[1] = 0; g_barD = 0; }
}
__global__ void combine(){
    int i = blockIdx.x*blockDim.x+threadIdx.x;
    if (i >= 128*HID) return;
    int m = i/HID, c = i%HID;
    float h = g_hFe[0][0][i] + g_hFe[1][0][i];
    g_d0F[i] = h;
    __half hh = __float2half(h);
    g_d0A[(size_t)m*KP2 + c]       = hh;
    g_d0A[(size_t)m*KP2 + HID + c] = __float2half(h - __half2float(hh));
}

// ----------------------------- MMA core (R5-proven) ------------------------
template<int SK>
__device__ __forceinline__ void mma_core(uint32_t smA32, uint32_t smW32,
    const char* const* asrc, const uint32_t* adst,
    const char* const* wsrc, const uint32_t* wdst,
    int arow_l, int a_kb, int brow_l, int b_kb, float (&acc)[4][3][4])
{
#pragma unroll
    for (int a=0;a<4;a++)
#pragma unroll
        for (int b=0;b<3;b++)
#pragma unroll
            for (int c=0;c<4;c++) acc[a][b][c]=0.f;

    auto load_stage = [&](int s){
        int b = s & (DEPTH-1);
        uint32_t dA = smA32 + b*ASTG, dW = smW32 + b*WSTG;
        size_t off = (size_t)s*128;
#pragma unroll
        for (int i=0;i<4;i++) CP16(dA+adst[i], asrc[i]+off);
#pragma unroll
        for (int i=0;i<3;i++) CP16(dW+wdst[i], wsrc[i]+off);
        CPCOMMIT();
    };
    load_stage(0); load_stage(1); load_stage(2);

    for (int s=0; s<SK; s++){
        if (s < SK-2)      CPWAIT(2);
        else if (s==SK-2)  CPWAIT(1);
        else               CPWAIT(0);
        __syncthreads();
        if (s+3 < SK) load_stage(s+3);
        int b = s & (DEPTH-1);
        uint32_t aB = smA32 + b*ASTG, wB = smW32 + b*WSTG;
#pragma unroll
        for (int kk=0; kk<4; kk++){
            uint32_t aF[4][4], bF[3][2];
#pragma unroll
            for (int mi=0; mi<4; mi++)
                LDSM4(aF[mi], aB + SWZ((uint32_t)((arow_l+mi*16)*128 + kk*32 + a_kb)));
#pragma unroll
            for (int ni=0; ni<3; ni++)
                LDSM2(bF[ni], wB + SWZ((uint32_t)((brow_l+ni*8)*128 + kk*32 + b_kb)));
#pragma unroll
            for (int mi=0;mi<4;mi++)
#pragma unroll
                for (int ni=0;ni<3;ni++)
                    MMA16816(acc[mi][ni], aF[mi], bF[ni]);
        }
    }
    __syncthreads();
}

// --------------------------- bulk HMMA GEMM --------------------------------
// MODE 0: U_enc grid(32,31,2) | MODE 1: U_dec grid(32,5,1) | MODE 4: FC grid(6,90,1)
template<int MODE>
__global__ void __launch_bounds__(256) gk(const float* __restrict__ fcb,
                                          float* __restrict__ outp)
{
    constexpr int KPT = (MODE==0)?KPE2:KP2;
    constexpr int SK  = KPT/64;
    const int nx = blockIdx.x, my = blockIdx.y, z = blockIdx.z;
    const int tid = threadIdx.x;
    const int w = tid>>5, lane = tid&31;
    const int wm = w&1, wn = w>>1;

    extern __shared__ __align__(16) char sm[];
    uint32_t smA32 = smem_u32(sm);
    uint32_t smW32 = smA32 + DEPTH*ASTG;

    const char* asrc[4]; uint32_t adst[4];
    const char* wsrc[3]; uint32_t wdst[3];
#pragma unroll
    for (int i=0;i<4;i++){
        int id = tid + 256*i, r = id>>3, c = id&7;
        const __half* p;
        if (MODE==0){ int v=my*128+r; if(v>=VOC) v=0; p=g_embE+(size_t)v*KPE2; }
        else if (MODE==1){ int v=my*128+r; if(v>=PON) v=0; p=g_embD+(size_t)v*KP2; }
        else { p=g_fcA+(size_t)(my*128+r)*KP2; }
        asrc[i] = (const char*)p + c*16;
        adst[i] = SWZ((uint32_t)(r*128 + c*16));
    }
    {
        const __half* Wb = (MODE==0)?g_WihIe[z]:(MODE==1)?g_WihId:g_Wfc;
#pragma unroll
        for (int i=0;i<3;i++){
            int id = tid + 256*i, r = id>>3, c = id&7;
            wsrc[i] = (const char*)(Wb + (size_t)(nx*96+r)*KPT) + c*16;
            wdst[i] = SWZ((uint32_t)(r*128 + c*16));
        }
    }
    const int arow_l = wm*64 + (lane&15);
    const int a_kb   = (lane>>4)*16;
    const int brow_l = wn*24 + (lane&7);
    const int b_kb   = ((lane>>3)&1)*16;

    float acc[4][3][4];
    mma_core<SK>(smA32, smW32, asrc, adst, wsrc, wdst, arow_l, a_kb, brow_l, b_kb, acc);

    const int gr = lane>>2, gc = (lane&3)*2;
    if (MODE==0 || MODE==1){
        const float* bi = (MODE==0)? g_bihE[z] : g_bihD;
        float* Ub = (MODE==0)? g_Ue[z] : g_Ud;
        const int vreal = (MODE==0)? VOC : PON;
#pragma unroll
        for (int mi=0;mi<4;mi++)
#pragma unroll
            for (int h=0;h<2;h++){
                int m = wm*64+mi*16+gr+h*8;
                int v = my*128+m;
                if (v < vreal){
#pragma unroll
                    for (int ni=0;ni<3;ni++){
                        int n = nx*96 + wn*24 + ni*8 + gc;
                        float2 val = { acc[mi][ni][h*2+0]+bi[n], acc[mi][ni][h*2+1]+bi[n+1] };
                        *(float2*)&Ub[(size_t)v*H3 + n] = val;
                    }
                }
            }
    } else {
#pragma unroll
        for (int mi=0;mi<4;mi++)
#pragma unroll
            for (int h=0;h<2;h++){
                int mm = my*128 + wm*64+mi*16+gr+h*8;
#pragma unroll
                for (int ni=0;ni<3;ni++){
                    int n = nx*96 + wn*24 + ni*8 + gc;
                    if (n < PON){
                        float2 val = { acc[mi][ni][h*2+0]+fcb[n], acc[mi][ni][h*2+1]+fcb[n+1] };
                        *(float2*)&outp[(size_t)mm*PON + n] = val;
                    }
                }
            }
    }
}

// ---------------------- persistent recurrent kernels -----------------------
// Encoder: 256 CTAs (32nx x 4ks x 2dir), 114688B smem -> 2 CTAs/SM for
// latency hiding. A and W both stream through 4-deep rings. Epilogue inputs
// prefetched before the barrier; gates via tanh.approx.
__global__ void __launch_bounds__(256,2) enc_run(const int* __restrict__ idx)
{
    const int cta = blockIdx.x;                 // 256 CTAs
    const int z = cta>>7, rem = cta&127, nx = rem&31, ks = rem>>5;  // ks 0..3
    const int tid = threadIdx.x, w = tid>>5, lane = tid&31, wm = w&1, wn = w>>1;
    extern __shared__ __align__(16) char sm[];
    uint32_t smA32 = smem_u32(sm), smW32 = smA32 + DEPTH*ASTG;
    constexpr int KCH = KP2/KS_ENC;             // 512
    constexpr int SK  = SK_E;                   // 8
    const size_t kb0 = (size_t)ks*KCH*2;
    int* mybar = &g_barE[z];

    const char* wsrc[3]; uint32_t wdst[3];
#pragma unroll
    for (int i=0;i<3;i++){
        int id=tid+256*i, r=id>>3, c=id&7;
        wsrc[i] = (const char*)(g_WhhI[z] + (size_t)(nx*96+r)*KP2) + kb0 + c*16;
        wdst[i] = SWZ((uint32_t)(r*128+c*16));
    }
    size_t aoff[4]; uint32_t adst[4];
#pragma unroll
    for (int i=0;i<4;i++){
        int id=tid+256*i, r=id>>3, c=id&7;
        aoff[i] = (size_t)r*KP2*2 + kb0 + c*16;
        adst[i] = SWZ((uint32_t)(r*128+c*16));
    }
    const int arow_l = wm*64 + (lane&15);
    const int a_kb   = (lane>>4)*16;
    const int brow_l = wn*24 + (lane&7);
    const int b_kb   = ((lane>>3)&1)*16;
    const int gr = lane>>2, gc = (lane&3)*2;

    const int u = lane, xu = nx*32+u;
    const float br = g_bhhI[z][nx*96+u];
    const float bz = g_bhhI[z][nx*96+32+u];
    const float bn = g_bhhI[z][nx*96+64+u];
    const float* U = g_Ue[z];
    float* pb = g_part[z][ks][nx];

    for (int t=0; t<TIN; t++){
        const char* abase = (const char*)g_hAe[z][t&1];
        const char* asrc[4];
#pragma unroll
        for (int i=0;i<4;i++) asrc[i] = abase + aoff[i];

        float acc[4][3][4];
        mma_core<SK>(smA32, smW32, asrc, adst, wsrc, wdst, arow_l, a_kb, brow_l, b_kb, acc);

#pragma unroll
        for (int mi=0;mi<4;mi++)
#pragma unroll
            for (int h=0;h<2;h++){
                int m = wm*64+mi*16+gr+h*8;
#pragma unroll
                for (int ni=0;ni<3;ni++){
                    int n = wn*24+ni*8+gc;
                    float2 v = { acc[mi][ni][h*2], acc[mi][ni][h*2+1] };
                    *(float2*)&pb[m*96+n] = v;
                }
            }

        // ---- prefetch barrier-independent epilogue inputs ----
        const float* hin  = g_hFe[z][t&1];
        float* hout = g_hFe[z][(t&1)^1];
        __half* hA = g_hAe[z][(t&1)^1];
        float pUr[4], pUz[4], pUn[4], phv[4];
#pragma unroll
        for (int i=0;i<4;i++){
            int m = ks*32 + w*4 + i;
            int tok = idx[m*TIN + t];
            const float* Urow = U + (size_t)tok*H3 + nx*96;
            pUr[i] = Urow[u];
            pUz[i] = Urow[32+u];
            pUn[i] = Urow[64+u];
            phv[i] = hin[(size_t)m*HID + xu];
        }

        bar_sync(mybar, 128*(2*t+1));
        // distributed epilogue: this CTA does m in [ks*32, ks*32+32), u = lane
#pragma unroll
        for (int i=0;i<4;i++){
            int m = ks*32 + w*4 + i;
            float sr=0.f, sz=0.f, sn=0.f;
#pragma unroll
            for (int k2=0;k2<KS_ENC;k2++){
                const float* pp = g_part[z][k2][nx] + m*96;
                sr += pp[u]; sz += pp[32+u]; sn += pp[64+u];
            }
            float rr = sigmoid_fast(pUr[i] + sr + br);
            float zz = sigmoid_fast(pUz[i] + sz + bz);
            float nn = tanh_fast(pUn[i] + rr*(sn + bn));
            float h  = (1.f-zz)*nn + zz*phv[i];
            hout[(size_t)m*HID + xu] = h;
            __half hh = __float2half(h);
            hA[(size_t)m*KP2 + xu]       = hh;
            hA[(size_t)m*KP2 + HID + xu] = __float2half(h - __half2float(hh));
        }
        bar_sync(mybar, 128*(2*t+2));
    }
}

// Decoder: W chunk (96 x 512 fp16 = 96KB) fully resident; A streams via ring.
__global__ void __launch_bounds__(256) dec_run(const int* __restrict__ idx)
{
    const int cta = blockIdx.x;                 // 128 CTAs
    const int nx = cta & 31, ks = cta>>5;       // ks 0..3
    const int tid = threadIdx.x, w = tid>>5, lane = tid&31, wm = w&1, wn = w>>1;
    extern __shared__ __align__(16) char sm[];
    uint32_t smA32 = smem_u32(sm), smW32 = smA32 + DEPTH*ASTG;
    constexpr int KCH = KP2/KS_DEC;             // 512
    constexpr int SK  = SK_D;                   // 8
    const size_t kb0 = (size_t)ks*KCH*2;

    // ---- load W resident (8 stages x 12KB) ----
    {
        const char* wsrc[3]; uint32_t wdst[3];
#pragma unroll
        for (int i=0;i<3;i++){
            int id=tid+256*i, r=id>>3, c=id&7;
            wsrc[i] = (const char*)(g_WhhI[2] + (size_t)(nx*96+r)*KP2) + kb0 + c*16;
            wdst[i] = SWZ((uint32_t)(r*128+c*16));
        }
        for (int s=0;s<SK;s++){
#pragma unroll
            for (int i=0;i<3;i++)
                CP16(smW32 + s*WSTG + wdst[i], wsrc[i] + (size_t)s*128);
        }
        CPCOMMIT();
        CPWAIT(0);
        __syncthreads();
    }

    size_t aoff[4]; uint32_t adst[4];
#pragma unroll
    for (int i=0;i<4;i++){
        int id=tid+256*i, r=id>>3, c=id&7;
        aoff[i] = (size_t)r*KP2*2 + kb0 + c*16;
        adst[i] = SWZ((uint32_t)(r*128+c*16));
    }
    const int arow_l = wm*64 + (lane&15);
    const int a_kb   = (lane>>4)*16;
    const int brow_l = wn*24 + (lane&7);
    const int b_kb   = ((lane>>3)&1)*16;
    const int gr = lane>>2, gc = (lane&3)*2;

    const int u = lane, xu = nx*32+u;
    const float br = g_bhhI[2][nx*96+u];
    const float bz = g_bhhI[2][nx*96+32+u];
    const float bn = g_bhhI[2][nx*96+64+u];
    float* pb = g_part[0][ks][nx];

    for (int t=0; t<TOUT; t++){
        const char* abase = (t==0) ? (const char*)g_d0A
                                   : (const char*)(g_fcA + (size_t)(t-1)*128*KP2);
        const char* asrc[4];
#pragma unroll
        for (int i=0;i<4;i++) asrc[i] = abase + aoff[i];

        float acc[4][3][4];
#pragma unroll
        for (int a=0;a<4;a++)
#pragma unroll
            for (int b=0;b<3;b++)
#pragma unroll
                for (int c=0;c<4;c++) acc[a][b][c]=0.f;

        auto load_stage = [&](int s){
            uint32_t dA = smA32 + (s & (DEPTH-1))*ASTG;
            size_t off = (size_t)s*128;
#pragma unroll
            for (int i=0;i<4;i++) CP16(dA+adst[i], asrc[i]+off);
            CPCOMMIT();
        };
        load_stage(0); load_stage(1); load_stage(2);

        for (int s=0; s<SK; s++){
            if (s < SK-2)      CPWAIT(2);
            else if (s==SK-2)  CPWAIT(1);
            else               CPWAIT(0);
            __syncthreads();
            if (s+3 < SK) load_stage(s+3);
            uint32_t aB = smA32 + (s & (DEPTH-1))*ASTG;
            uint32_t wB = smW32 + s*WSTG;
#pragma unroll
            for (int kk=0; kk<4; kk++){
                uint32_t aF[4][4], bF[3][2];
#pragma unroll
                for (int mi=0; mi<4; mi++)
                    LDSM4(aF[mi], aB + SWZ((uint32_t)((arow_l+mi*16)*128 + kk*32 + a_kb)));
#pragma unroll
                for (int ni=0; ni<3; ni++)
                    LDSM2(bF[ni], wB + SWZ((uint32_t)((brow_l+ni*8)*128 + kk*32 + b_kb)));
#pragma unroll
                for (int mi=0;mi<4;mi++)
#pragma unroll
                    for (int ni=0;ni<3;ni++)
                        MMA16816(acc[mi][ni], aF[mi], bF[ni]);
            }
        }
        __syncthreads();

#pragma unroll
        for (int mi=0;mi<4;mi++)
#pragma unroll
            for (int h=0;h<2;h++){
                int m = wm*64+mi*16+gr+h*8;
#pragma unroll
                for (int ni=0;ni<3;ni++){
                    int n = wn*24+ni*8+gc;
                    float2 v = { acc[mi][ni][h*2], acc[mi][ni][h*2+1] };
                    *(float2*)&pb[m*96+n] = v;
                }
            }

        // ---- prefetch barrier-independent epilogue inputs ----
        const float* hin  = t ? g_hFd[(t-1)&1] : g_d0F;
        float* hout = g_hFd[t&1];
        __half* hA = g_fcA + (size_t)t*128*KP2;
        int ti = t ? t-1 : 0;
        float pUr[4], pUz[4], pUn[4], phv[4];
#pragma unroll
        for (int i=0;i<4;i++){
            int m = ks*32 + w + i*8;
            int tok = idx[m*TOUT + ti];
            const float* Urow = g_Ud + (size_t)tok*H3 + nx*96;
            pUr[i] = Urow[u];
            pUz[i] = Urow[32+u];
            pUn[i] = Urow[64+u];
            phv[i] = hin[(size_t)m*HID + xu];
        }

        bar_sync(&g_barD, 128*(2*t+1));
        // distributed epilogue: m in [ks*32, ks*32+32), u = lane
#pragma unroll
        for (int i=0;i<4;i++){
            int m = ks*32 + w + i*8;
            float sr=0.f, sz=0.f, sn=0.f;
#pragma unroll
            for (int k2=0;k2<KS_DEC;k2++){
                const float* pp = g_part[0][k2][nx] + m*96;
                sr += pp[u]; sz += pp[32+u]; sn += pp[64+u];
            }
            float rr = sigmoid_fast(pUr[i] + sr + br);
            float zz = sigmoid_fast(pUz[i] + sz + bz);
            float nn = tanh_fast(pUn[i] + rr*(sn + bn));
            float h  = (1.f-zz)*nn + zz*phv[i];
            hout[(size_t)m*HID + xu] = h;
            __half hh = __float2half(h);
            hA[(size_t)m*KP2 + xu]       = hh;
            hA[(size_t)m*KP2 + HID + xu] = __float2half(h - __half2float(hh));
        }
        bar_sync(&g_barD, 128*(2*t+2));
    }
}

// ------------------------------- launch ------------------------------------
extern "C" void kernel_launch(void* const* d_in, const int* in_sizes, int n_in,
                              void* d_out, int out_size)
{
    const float* enc_emb   = (const float*)d_in[0];
    const float* enc_Wih_f = (const float*)d_in[1];
    const float* enc_Whh_f = (const float*)d_in[2];
    const float* enc_bih_f = (const float*)d_in[3];
    const float* enc_bhh_f = (const float*)d_in[4];
    const float* enc_Wih_b = (const float*)d_in[5];
    const float* enc_Whh_b = (const float*)d_in[6];
    const float* enc_bih_b = (const float*)d_in[7];
    const float* enc_bhh_b = (const float*)d_in[8];
    const float* dec_emb   = (const float*)d_in[9];
    const float* dec_Wih   = (const float*)d_in[10];
    const float* dec_Whh   = (const float*)d_in[11];
    const float* dec_bih   = (const float*)d_in[12];
    const float* dec_bhh   = (const float*)d_in[13];
    const float* fc_W      = (const float*)d_in[14];
    const float* fc_b      = (const float*)d_in[15];
    const int*   in_text   = (const int*)d_in[16];
    const int*   poses     = (const int*)d_in[18];
    float* out = (float*)d_out;

    cudaFuncSetAttribute(gk<0>,  cudaFuncAttributeMaxDynamicSharedMemorySize, SMTOT);
    cudaFuncSetAttribute(gk<1>,  cudaFuncAttributeMaxDynamicSharedMemorySize, SMTOT);
    cudaFuncSetAttribute(gk<4>,  cudaFuncAttributeMaxDynamicSharedMemorySize, SMTOT);
    cudaFuncSetAttribute(enc_run, cudaFuncAttributeMaxDynamicSharedMemorySize, SMTOT);
    cudaFuncSetAttribute(dec_run, cudaFuncAttributeMaxDynamicSharedMemorySize, SMTOT_D);

    prep_a<<<dim3(128,2),256>>>(enc_emb, dec_emb);
    prep_w<<<dim3(256,7),256>>>(enc_Wih_f, enc_bih_f, enc_Wih_b, enc_bih_b,
                                dec_Wih, dec_bih, enc_Whh_f, enc_bhh_f,
                                enc_Whh_b, enc_bhh_b, dec_Whh, dec_bhh, fc_W);
    init_h<<<(128*KP2+255)/256,256>>>();

    gk<0><<<dim3(32,31,2),256,SMTOT>>>(nullptr, nullptr);
    gk<1><<<dim3(32,5,1), 256,SMTOT>>>(nullptr, nullptr);

    enc_run<<<256,256,SMTOT>>>(in_text);
    combine<<<(128*HID+255)/256,256>>>();
    dec_run<<<128,256,SMTOT_D>>>(poses);

    gk<4><<<dim3(6,90,1),256,SMTOT>>>(fc_b, out);
}

// round 17
// speedup vs baseline: 1.5133x; 1.5133x over previous
#include <cuda_runtime.h>
#include <cuda_fp16.h>
#include <math.h>
#include <stdint.h>

#define HID  1024
#define H3   3072
#define VOC  3863
#define VOCP 3968
#define PON  514
#define PONP 640
#define TIN  64
#define TOUT 90
#define KP2  2048
#define KPE2 640
#define KS_ENC 2
#define KS_DEC 4
#define DEPTH 4
#define ASTG 16384
#define WSTG 12288
#define RES_E 9
#define SK_E 16
#define SK_D 8
#define SMTOT   (DEPTH*(ASTG+WSTG))                    // 114688 (bulk)
#define SMTOT_E (DEPTH*ASTG + DEPTH*WSTG + RES_E*WSTG) // 225280 (enc)
#define SMTOT_D (DEPTH*ASTG + SK_D*WSTG)               // 163840 (dec)

// ------------------------- device-global scratch ---------------------------
__device__ __half g_WhhI[3][H3*KP2];       // interleaved rows, K' = [hi|hi]
__device__ __half g_WihIe[2][H3*KPE2];
__device__ __half g_WihId[H3*KP2];
__device__ __half g_Wfc[576*HID];          // single hi segment (K=1024)
__device__ __half g_embE[VOCP*KPE2];       // K' = [hi|lo] (A exact)
__device__ __half g_embD[PONP*KP2];
__device__ float g_Ue[2][(size_t)VOCP*H3]; // input-gate tables (interleaved cols)
__device__ float g_Ud[(size_t)PONP*H3];
__device__ float g_bihE[2][H3];
__device__ float g_bihD[H3];
__device__ float g_bhhI[3][H3];
__device__ __half g_hAe[2][2][128*KP2];    // encoder h split A, ping-pong
__device__ float g_hFe[2][2][128*HID];
__device__ float g_hFd[2][128*HID];
__device__ float g_d0F[128*HID];
__device__ __half g_d0A[128*KP2];
__device__ __half g_fcA[(size_t)TOUT*128*KP2];  // decoder states (split) = FC input
__device__ float g_part[2][4][32][128*96]; // [z][ks][nx][m*96+n]
__device__ int   g_barE[2], g_barD;        // grid barriers (monotonic)

// ------------------------------ asm helpers --------------------------------
__device__ __forceinline__ uint32_t smem_u32(const void* p){
    uint32_t a;
    asm("{ .reg .u64 t; cvta.to.shared.u64 t, %1; cvt.u32.u64 %0, t; }":"=r"(a):"l"(p));
    return a;
}
__device__ __forceinline__ float tanh_fast(float x){
    float r;
    asm("tanh.approx.f32 %0, %1;" : "=f"(r) : "f"(x));
    return r;
}
__device__ __forceinline__ float sigmoid_fast(float x){
    return 0.5f*tanh_fast(0.5f*x) + 0.5f;
}
#define SWZ(x) ((x) ^ (((x) >> 3) & 0x70))
#define CP16(d_, s_) asm volatile("cp.async.cg.shared.global [%0], [%1], 16;"::"r"(d_),"l"(s_))
#define CPCOMMIT()   asm volatile("cp.async.commit_group;":::"memory")
#define CPWAIT(n)    asm volatile("cp.async.wait_group %0;"::"n"(n):"memory")
#define LDSM4(r, a) \
    asm volatile("ldmatrix.sync.aligned.m8n8.x4.shared.b16 {%0,%1,%2,%3}, [%4];" \
        : "=r"((r)[0]),"=r"((r)[1]),"=r"((r)[2]),"=r"((r)[3]) : "r"(a))
#define LDSM2(r, a) \
    asm volatile("ldmatrix.sync.aligned.m8n8.x2.shared.b16 {%0,%1}, [%2];" \
        : "=r"((r)[0]),"=r"((r)[1]) : "r"(a))
#define MMA16816(d, a, b) \
    asm volatile("mma.sync.aligned.m16n8k16.row.col.f32.f16.f16.f32 " \
        "{%0,%1,%2,%3}, {%4,%5,%6,%7}, {%8,%9}, {%0,%1,%2,%3};" \
        : "+f"((d)[0]),"+f"((d)[1]),"+f"((d)[2]),"+f"((d)[3]) \
        : "r"((a)[0]),"r"((a)[1]),"r"((a)[2]),"r"((a)[3]),"r"((b)[0]),"r"((b)[1]))

// grid-wide barrier: monotonic counter, fence + add + volatile spin
__device__ __forceinline__ void bar_sync(int* bar, int target)
{
    __threadfence();
    __syncthreads();
    if (threadIdx.x == 0){
        atomicAdd(bar, 1);
        while (*(volatile int*)bar < target)
            asm volatile("nanosleep.u32 32;");
        __threadfence();
    }
    __syncthreads();
}

// ------------------------------ prep kernels -------------------------------
// W: fp16 hi duplicated in both K' segments (W rounded once; A side exact).
// Wfc (which==6): single hi segment, K=1024.
__global__ void prep_w(const float* s0,const float* b0,const float* s1,const float* b1,
                       const float* s2,const float* b2,const float* s3,const float* b3,
                       const float* s4,const float* b4,const float* s5,const float* b5,
                       const float* s6)
{
    int which = blockIdx.y;
    const float* src; const float* bs = nullptr;
    __half* dst; float* bd = nullptr;
    int Nrows=H3, realR=H3, K=HID, Kpad=HID, inter=1, segs=2;
    switch(which){
        case 0: src=s0; bs=b0; dst=g_WihIe[0]; bd=g_bihE[0]; K=300; Kpad=320; break;
        case 1: src=s1; bs=b1; dst=g_WihIe[1]; bd=g_bihE[1]; K=300; Kpad=320; break;
        case 2: src=s2; bs=b2; dst=g_WihId;    bd=g_bihD;    break;
        case 3: src=s3; bs=b3; dst=g_WhhI[0];  bd=g_bhhI[0]; break;
        case 4: src=s4; bs=b4; dst=g_WhhI[1];  bd=g_bhhI[1]; break;
        case 5: src=s5; bs=b5; dst=g_WhhI[2];  bd=g_bhhI[2]; break;
        default: src=s6; dst=g_Wfc; Nrows=576; realR=PON; inter=0; segs=1; break;
    }
    int KP = segs*Kpad;
    long total = (long)Nrows*KP;
    for (long o=(long)blockIdx.x*blockDim.x+threadIdx.x; o<total;
         o += (long)gridDim.x*blockDim.x){
        int nr=(int)(o/KP), kq=(int)(o%KP), kk=kq%Kpad;
        int gr;
        if (inter){ int x=nr/96, rem=nr%96, g=rem/32, u=rem%32; gr=g*HID + x*32 + u; }
        else gr = nr;
        float v = (kk<K && gr<realR) ? src[(size_t)gr*K+kk] : 0.f;
        dst[o] = __float2half(v);
        if (kq==0 && bd) bd[nr] = (gr<realR) ? bs[gr] : 0.f;
    }
}
// Embedding split: [hi | lo] (A exact across the two terms)
__global__ void prep_a(const float* srcE, const float* srcD)
{
    int which = blockIdx.y;
    const float* src; __half* dst; int R, realR, K, Kpad;
    if (which==0){ src=srcE; dst=g_embE; R=VOCP; realR=VOC; K=300; Kpad=320; }
    else         { src=srcD; dst=g_embD; R=PONP; realR=PON; K=HID; Kpad=HID; }
    int KP = 2*Kpad;
    long total = (long)R*KP;
    for (long o=(long)blockIdx.x*blockDim.x+threadIdx.x; o<total;
         o += (long)gridDim.x*blockDim.x){
        int r=(int)(o/KP), kq=(int)(o%KP), seg=kq/Kpad, kk=kq%Kpad;
        int gr = r<realR ? r : 0;
        float v = kk<K ? src[(size_t)gr*K+kk] : 0.f;
        __half hi = __float2half(v);
        dst[o] = (seg==1) ? __float2half(v - __half2float(hi)) : hi;
    }
}
__global__ void init_h(){
    int i = blockIdx.x*blockDim.x+threadIdx.x;
    if (i < 128*HID){ g_hFe[0][0][i]=0.f; g_hFe[1][0][i]=0.f; }
    if (i < 128*KP2){
        g_hAe[0][0][i]=__float2half(0.f);
        g_hAe[1][0][i]=__float2half(0.f);
    }
    if (i == 0){ g_barE[0] = 0; g_barE[1] = 0; g_barD = 0; }
}
__global__ void combine(){
    int i = blockIdx.x*blockDim.x+threadIdx.x;
    if (i >= 128*HID) return;
    int m = i/HID, c = i%HID;
    float h = g_hFe[0][0][i] + g_hFe[1][0][i];
    g_d0F[i] = h;
    __half hh = __float2half(h);
    g_d0A[(size_t)m*KP2 + c]       = hh;
    g_d0A[(size_t)m*KP2 + HID + c] = __float2half(h - __half2float(hh));
}

// ----------------------------- MMA core (R5-proven, bulk) ------------------
template<int SK>
__device__ __forceinline__ void mma_core(uint32_t smA32, uint32_t smW32,
    const char* const* asrc, const uint32_t* adst,
    const char* const* wsrc, const uint32_t* wdst,
    int arow_l, int a_kb, int brow_l, int b_kb, float (&acc)[4][3][4])
{
#pragma unroll
    for (int a=0;a<4;a++)
#pragma unroll
        for (int b=0;b<3;b++)
#pragma unroll
            for (int c=0;c<4;c++) acc[a][b][c]=0.f;

    auto load_stage = [&](int s){
        int b = s & (DEPTH-1);
        uint32_t dA = smA32 + b*ASTG, dW = smW32 + b*WSTG;
        size_t off = (size_t)s*128;
#pragma unroll
        for (int i=0;i<4;i++) CP16(dA+adst[i], asrc[i]+off);
#pragma unroll
        for (int i=0;i<3;i++) CP16(dW+wdst[i], wsrc[i]+off);
        CPCOMMIT();
    };
    load_stage(0); load_stage(1); load_stage(2);

    for (int s=0; s<SK; s++){
        if (s < SK-2)      CPWAIT(2);
        else if (s==SK-2)  CPWAIT(1);
        else               CPWAIT(0);
        __syncthreads();
        if (s+3 < SK) load_stage(s+3);
        int b = s & (DEPTH-1);
        uint32_t aB = smA32 + b*ASTG, wB = smW32 + b*WSTG;
#pragma unroll
        for (int kk=0; kk<4; kk++){
            uint32_t aF[4][4], bF[3][2];
#pragma unroll
            for (int mi=0; mi<4; mi++)
                LDSM4(aF[mi], aB + SWZ((uint32_t)((arow_l+mi*16)*128 + kk*32 + a_kb)));
#pragma unroll
            for (int ni=0; ni<3; ni++)
                LDSM2(bF[ni], wB + SWZ((uint32_t)((brow_l+ni*8)*128 + kk*32 + b_kb)));
#pragma unroll
            for (int mi=0;mi<4;mi++)
#pragma unroll
                for (int ni=0;ni<3;ni++)
                    MMA16816(acc[mi][ni], aF[mi], bF[ni]);
        }
    }
    __syncthreads();
}

// --------------------------- bulk HMMA GEMM --------------------------------
// MODE 0: U_enc grid(32,31,2) | MODE 1: U_dec grid(32,5,1) | MODE 4: FC grid(6,90,1)
template<int MODE>
__global__ void __launch_bounds__(256) gk(const float* __restrict__ fcb,
                                          float* __restrict__ outp)
{
    constexpr int KPW = (MODE==0)?KPE2:(MODE==4)?HID:KP2;  // W row stride / K extent
    constexpr int SK  = KPW/64;
    const int nx = blockIdx.x, my = blockIdx.y, z = blockIdx.z;
    const int tid = threadIdx.x;
    const int w = tid>>5, lane = tid&31;
    const int wm = w&1, wn = w>>1;

    extern __shared__ __align__(16) char sm[];
    uint32_t smA32 = smem_u32(sm);
    uint32_t smW32 = smA32 + DEPTH*ASTG;

    const char* asrc[4]; uint32_t adst[4];
    const char* wsrc[3]; uint32_t wdst[3];
#pragma unroll
    for (int i=0;i<4;i++){
        int id = tid + 256*i, r = id>>3, c = id&7;
        const __half* p;
        if (MODE==0){ int v=my*128+r; if(v>=VOC) v=0; p=g_embE+(size_t)v*KPE2; }
        else if (MODE==1){ int v=my*128+r; if(v>=PON) v=0; p=g_embD+(size_t)v*KP2; }
        else { p=g_fcA+(size_t)(my*128+r)*KP2; }   // reads only hi segment (SK=16)
        asrc[i] = (const char*)p + c*16;
        adst[i] = SWZ((uint32_t)(r*128 + c*16));
    }
    {
        const __half* Wb = (MODE==0)?g_WihIe[z]:(MODE==1)?g_WihId:g_Wfc;
#pragma unroll
        for (int i=0;i<3;i++){
            int id = tid + 256*i, r = id>>3, c = id&7;
            wsrc[i] = (const char*)(Wb + (size_t)(nx*96+r)*KPW) + c*16;
            wdst[i] = SWZ((uint32_t)(r*128 + c*16));
        }
    }
    const int arow_l = wm*64 + (lane&15);
    const int a_kb   = (lane>>4)*16;
    const int brow_l = wn*24 + (lane&7);
    const int b_kb   = ((lane>>3)&1)*16;

    float acc[4][3][4];
    mma_core<SK>(smA32, smW32, asrc, adst, wsrc, wdst, arow_l, a_kb, brow_l, b_kb, acc);

    const int gr = lane>>2, gc = (lane&3)*2;
    if (MODE==0 || MODE==1){
        const float* bi = (MODE==0)? g_bihE[z] : g_bihD;
        float* Ub = (MODE==0)? g_Ue[z] : g_Ud;
        const int vreal = (MODE==0)? VOC : PON;
#pragma unroll
        for (int mi=0;mi<4;mi++)
#pragma unroll
            for (int h=0;h<2;h++){
                int m = wm*64+mi*16+gr+h*8;
                int v = my*128+m;
                if (v < vreal){
#pragma unroll
                    for (int ni=0;ni<3;ni++){
                        int n = nx*96 + wn*24 + ni*8 + gc;
                        float2 val = { acc[mi][ni][h*2+0]+bi[n], acc[mi][ni][h*2+1]+bi[n+1] };
                        *(float2*)&Ub[(size_t)v*H3 + n] = val;
                    }
                }
            }
    } else {
#pragma unroll
        for (int mi=0;mi<4;mi++)
#pragma unroll
            for (int h=0;h<2;h++){
                int mm = my*128 + wm*64+mi*16+gr+h*8;
#pragma unroll
                for (int ni=0;ni<3;ni++){
                    int n = nx*96 + wn*24 + ni*8 + gc;
                    if (n < PON){
                        float2 val = { acc[mi][ni][h*2+0]+fcb[n], acc[mi][ni][h*2+1]+fcb[n+1] };
                        *(float2*)&outp[(size_t)mm*PON + n] = val;
                    }
                }
            }
    }
}

// ---------------------- persistent recurrent kernels -----------------------
// Encoder: W stages 0..RES_E-1 resident (loaded once); stages RES_E..SK_E-1
// stream through a 4-deep W ring. A streams through a 4-deep ring each step.
// Epilogue U/h loads prefetched before the barrier; gates via tanh.approx.
__global__ void __launch_bounds__(256) enc_run(const int* __restrict__ idx)
{
    const int cta = blockIdx.x;                 // 128 CTAs
    const int nx = cta & 31, ks = (cta>>5)&1, z = cta>>6;
    const int tid = threadIdx.x, w = tid>>5, lane = tid&31, wm = w&1, wn = w>>1;
    extern __shared__ __align__(16) char sm[];
    uint32_t smA32   = smem_u32(sm);
    uint32_t smWring = smA32 + DEPTH*ASTG;
    uint32_t smWres  = smWring + DEPTH*WSTG;
    constexpr int KCH = KP2/KS_ENC;             // 1024
    constexpr int SK  = SK_E;                   // 16
    const size_t kb0 = (size_t)ks*KCH*2;
    int* mybar = &g_barE[z];

    const char* wsrc[3]; uint32_t wdst[3];
#pragma unroll
    for (int i=0;i<3;i++){
        int id=tid+256*i, r=id>>3, c=id&7;
        wsrc[i] = (const char*)(g_WhhI[z] + (size_t)(nx*96+r)*KP2) + kb0 + c*16;
        wdst[i] = SWZ((uint32_t)(r*128+c*16));
    }
    // ---- one-time resident W load (stages 0..RES_E-1) ----
    for (int s=0;s<RES_E;s++){
#pragma unroll
        for (int i=0;i<3;i++)
            CP16(smWres + s*WSTG + wdst[i], wsrc[i] + (size_t)s*128);
    }
    CPCOMMIT();
    CPWAIT(0);
    __syncthreads();

    size_t aoff[4]; uint32_t adst[4];
#pragma unroll
    for (int i=0;i<4;i++){
        int id=tid+256*i, r=id>>3, c=id&7;
        aoff[i] = (size_t)r*KP2*2 + kb0 + c*16;
        adst[i] = SWZ((uint32_t)(r*128+c*16));
    }
    const int arow_l = wm*64 + (lane&15);
    const int a_kb   = (lane>>4)*16;
    const int brow_l = wn*24 + (lane&7);
    const int b_kb   = ((lane>>3)&1)*16;
    const int gr = lane>>2, gc = (lane&3)*2;

    const int u = lane, xu = nx*32+u;
    const float br = g_bhhI[z][nx*96+u];
    const float bz = g_bhhI[z][nx*96+32+u];
    const float bn = g_bhhI[z][nx*96+64+u];
    const float* U = g_Ue[z];
    float* pb = g_part[z][ks][nx];

    for (int t=0; t<TIN; t++){
        const char* abase = (const char*)g_hAe[z][t&1];
        const char* asrc[4];
#pragma unroll
        for (int i=0;i<4;i++) asrc[i] = abase + aoff[i];

        float acc[4][3][4];
#pragma unroll
        for (int a=0;a<4;a++)
#pragma unroll
            for (int b=0;b<3;b++)
#pragma unroll
                for (int c=0;c<4;c++) acc[a][b][c]=0.f;

        auto load_stage = [&](int s){
            uint32_t dA = smA32 + (s & (DEPTH-1))*ASTG;
            size_t off = (size_t)s*128;
#pragma unroll
            for (int i=0;i<4;i++) CP16(dA+adst[i], asrc[i]+off);
            if (s >= RES_E){
                uint32_t dW = smWring + (s & (DEPTH-1))*WSTG;
#pragma unroll
                for (int i=0;i<3;i++) CP16(dW+wdst[i], wsrc[i]+off);
            }
            CPCOMMIT();
        };
        load_stage(0); load_stage(1); load_stage(2);

        for (int s=0; s<SK; s++){
            if (s < SK-2)      CPWAIT(2);
            else if (s==SK-2)  CPWAIT(1);
            else               CPWAIT(0);
            __syncthreads();
            if (s+3 < SK) load_stage(s+3);
            uint32_t aB = smA32 + (s & (DEPTH-1))*ASTG;
            uint32_t wB = (s < RES_E) ? (smWres + s*WSTG)
                                      : (smWring + (s & (DEPTH-1))*WSTG);
#pragma unroll
            for (int kk=0; kk<4; kk++){
                uint32_t aF[4][4], bF[3][2];
#pragma unroll
                for (int mi=0; mi<4; mi++)
                    LDSM4(aF[mi], aB + SWZ((uint32_t)((arow_l+mi*16)*128 + kk*32 + a_kb)));
#pragma unroll
                for (int ni=0; ni<3; ni++)
                    LDSM2(bF[ni], wB + SWZ((uint32_t)((brow_l+ni*8)*128 + kk*32 + b_kb)));
#pragma unroll
                for (int mi=0;mi<4;mi++)
#pragma unroll
                    for (int ni=0;ni<3;ni++)
                        MMA16816(acc[mi][ni], aF[mi], bF[ni]);
            }
        }
        __syncthreads();

#pragma unroll
        for (int mi=0;mi<4;mi++)
#pragma unroll
            for (int h=0;h<2;h++){
                int m = wm*64+mi*16+gr+h*8;
#pragma unroll
                for (int ni=0;ni<3;ni++){
                    int n = wn*24+ni*8+gc;
                    float2 v = { acc[mi][ni][h*2], acc[mi][ni][h*2+1] };
                    *(float2*)&pb[m*96+n] = v;
                }
            }

        // ---- prefetch barrier-independent epilogue inputs ----
        const float* hin  = g_hFe[z][t&1];
        float* hout = g_hFe[z][(t&1)^1];
        __half* hA = g_hAe[z][(t&1)^1];
        float pUr[8], pUz[8], pUn[8], phv[8];
#pragma unroll
        for (int i=0;i<8;i++){
            int m = ks*64 + w + i*8;
            int tok = idx[m*TIN + t];
            const float* Urow = U + (size_t)tok*H3 + nx*96;
            pUr[i] = Urow[u];
            pUz[i] = Urow[32+u];
            pUn[i] = Urow[64+u];
            phv[i] = hin[(size_t)m*HID + xu];
        }

        bar_sync(mybar, 64*(2*t+1));
        // distributed epilogue: this CTA does m in [ks*64, ks*64+64), u = lane
#pragma unroll
        for (int i=0;i<8;i++){
            int m = ks*64 + w + i*8;
            const float* p0 = g_part[z][0][nx] + m*96;
            const float* p1 = g_part[z][1][nx] + m*96;
            float sr = p0[u]+p1[u], sz = p0[32+u]+p1[32+u], sn = p0[64+u]+p1[64+u];
            float rr = sigmoid_fast(pUr[i] + sr + br);
            float zz = sigmoid_fast(pUz[i] + sz + bz);
            float nn = tanh_fast(pUn[i] + rr*(sn + bn));
            float h  = (1.f-zz)*nn + zz*phv[i];
            hout[(size_t)m*HID + xu] = h;
            __half hh = __float2half(h);
            hA[(size_t)m*KP2 + xu]       = hh;
            hA[(size_t)m*KP2 + HID + xu] = __float2half(h - __half2float(hh));
        }
        bar_sync(mybar, 64*(2*t+2));
    }
}

// Decoder: W chunk (96 x 512 fp16 = 96KB) fully resident; A streams via ring.
__global__ void __launch_bounds__(256) dec_run(const int* __restrict__ idx)
{
    const int cta = blockIdx.x;                 // 128 CTAs
    const int nx = cta & 31, ks = cta>>5;       // ks 0..3
    const int tid = threadIdx.x, w = tid>>5, lane = tid&31, wm = w&1, wn = w>>1;
    extern __shared__ __align__(16) char sm[];
    uint32_t smA32 = smem_u32(sm), smW32 = smA32 + DEPTH*ASTG;
    constexpr int KCH = KP2/KS_DEC;             // 512
    constexpr int SK  = SK_D;                   // 8
    const size_t kb0 = (size_t)ks*KCH*2;

    // ---- load W resident (8 stages x 12KB) ----
    {
        const char* wsrc[3]; uint32_t wdst[3];
#pragma unroll
        for (int i=0;i<3;i++){
            int id=tid+256*i, r=id>>3, c=id&7;
            wsrc[i] = (const char*)(g_WhhI[2] + (size_t)(nx*96+r)*KP2) + kb0 + c*16;
            wdst[i] = SWZ((uint32_t)(r*128+c*16));
        }
        for (int s=0;s<SK;s++){
#pragma unroll
            for (int i=0;i<3;i++)
                CP16(smW32 + s*WSTG + wdst[i], wsrc[i] + (size_t)s*128);
        }
        CPCOMMIT();
        CPWAIT(0);
        __syncthreads();
    }

    size_t aoff[4]; uint32_t adst[4];
#pragma unroll
    for (int i=0;i<4;i++){
        int id=tid+256*i, r=id>>3, c=id&7;
        aoff[i] = (size_t)r*KP2*2 + kb0 + c*16;
        adst[i] = SWZ((uint32_t)(r*128+c*16));
    }
    const int arow_l = wm*64 + (lane&15);
    const int a_kb   = (lane>>4)*16;
    const int brow_l = wn*24 + (lane&7);
    const int b_kb   = ((lane>>3)&1)*16;
    const int gr = lane>>2, gc = (lane&3)*2;

    const int u = lane, xu = nx*32+u;
    const float br = g_bhhI[2][nx*96+u];
    const float bz = g_bhhI[2][nx*96+32+u];
    const float bn = g_bhhI[2][nx*96+64+u];
    float* pb = g_part[0][ks][nx];

    for (int t=0; t<TOUT; t++){
        const char* abase = (t==0) ? (const char*)g_d0A
                                   : (const char*)(g_fcA + (size_t)(t-1)*128*KP2);
        const char* asrc[4];
#pragma unroll
        for (int i=0;i<4;i++) asrc[i] = abase + aoff[i];

        float acc[4][3][4];
#pragma unroll
        for (int a=0;a<4;a++)
#pragma unroll
            for (int b=0;b<3;b++)
#pragma unroll
                for (int c=0;c<4;c++) acc[a][b][c]=0.f;

        auto load_stage = [&](int s){
            uint32_t dA = smA32 + (s & (DEPTH-1))*ASTG;
            size_t off = (size_t)s*128;
#pragma unroll
            for (int i=0;i<4;i++) CP16(dA+adst[i], asrc[i]+off);
            CPCOMMIT();
        };
        load_stage(0); load_stage(1); load_stage(2);

        for (int s=0; s<SK; s++){
            if (s < SK-2)      CPWAIT(2);
            else if (s==SK-2)  CPWAIT(1);
            else               CPWAIT(0);
            __syncthreads();
            if (s+3 < SK) load_stage(s+3);
            uint32_t aB = smA32 + (s & (DEPTH-1))*ASTG;
            uint32_t wB = smW32 + s*WSTG;
#pragma unroll
            for (int kk=0; kk<4; kk++){
                uint32_t aF[4][4], bF[3][2];
#pragma unroll
                for (int mi=0; mi<4; mi++)
                    LDSM4(aF[mi], aB + SWZ((uint32_t)((arow_l+mi*16)*128 + kk*32 + a_kb)));
#pragma unroll
                for (int ni=0; ni<3; ni++)
                    LDSM2(bF[ni], wB + SWZ((uint32_t)((brow_l+ni*8)*128 + kk*32 + b_kb)));
#pragma unroll
                for (int mi=0;mi<4;mi++)
#pragma unroll
                    for (int ni=0;ni<3;ni++)
                        MMA16816(acc[mi][ni], aF[mi], bF[ni]);
            }
        }
        __syncthreads();

#pragma unroll
        for (int mi=0;mi<4;mi++)
#pragma unroll
            for (int h=0;h<2;h++){
                int m = wm*64+mi*16+gr+h*8;
#pragma unroll
                for (int ni=0;ni<3;ni++){
                    int n = wn*24+ni*8+gc;
                    float2 v = { acc[mi][ni][h*2], acc[mi][ni][h*2+1] };
                    *(float2*)&pb[m*96+n] = v;
                }
            }

        // ---- prefetch barrier-independent epilogue inputs ----
        const float* hin  = t ? g_hFd[(t-1)&1] : g_d0F;
        float* hout = g_hFd[t&1];
        __half* hA = g_fcA + (size_t)t*128*KP2;
        int ti = t ? t-1 : 0;
        float pUr[4], pUz[4], pUn[4], phv[4];
#pragma unroll
        for (int i=0;i<4;i++){
            int m = ks*32 + w + i*8;
            int tok = idx[m*TOUT + ti];
            const float* Urow = g_Ud + (size_t)tok*H3 + nx*96;
            pUr[i] = Urow[u];
            pUz[i] = Urow[32+u];
            pUn[i] = Urow[64+u];
            phv[i] = hin[(size_t)m*HID + xu];
        }

        bar_sync(&g_barD, 128*(2*t+1));
        // distributed epilogue: m in [ks*32, ks*32+32), u = lane
#pragma unroll
        for (int i=0;i<4;i++){
            int m = ks*32 + w + i*8;
            float sr=0.f, sz=0.f, sn=0.f;
#pragma unroll
            for (int k2=0;k2<KS_DEC;k2++){
                const float* pp = g_part[0][k2][nx] + m*96;
                sr += pp[u]; sz += pp[32+u]; sn += pp[64+u];
            }
            float rr = sigmoid_fast(pUr[i] + sr + br);
            float zz = sigmoid_fast(pUz[i] + sz + bz);
            float nn = tanh_fast(pUn[i] + rr*(sn + bn));
            float h  = (1.f-zz)*nn + zz*phv[i];
            hout[(size_t)m*HID + xu] = h;
            __half hh = __float2half(h);
            hA[(size_t)m*KP2 + xu]       = hh;
            hA[(size_t)m*KP2 + HID + xu] = __float2half(h - __half2float(hh));
        }
        bar_sync(&g_barD, 128*(2*t+2));
    }
}

// ------------------------------- launch ------------------------------------
extern "C" void kernel_launch(void* const* d_in, const int* in_sizes, int n_in,
                              void* d_out, int out_size)
{
    const float* enc_emb   = (const float*)d_in[0];
    const float* enc_Wih_f = (const float*)d_in[1];
    const float* enc_Whh_f = (const float*)d_in[2];
    const float* enc_bih_f = (const float*)d_in[3];
    const float* enc_bhh_f = (const float*)d_in[4];
    const float* enc_Wih_b = (const float*)d_in[5];
    const float* enc_Whh_b = (const float*)d_in[6];
    const float* enc_bih_b = (const float*)d_in[7];
    const float* enc_bhh_b = (const float*)d_in[8];
    const float* dec_emb   = (const float*)d_in[9];
    const float* dec_Wih   = (const float*)d_in[10];
    const float* dec_Whh   = (const float*)d_in[11];
    const float* dec_bih   = (const float*)d_in[12];
    const float* dec_bhh   = (const float*)d_in[13];
    const float* fc_W      = (const float*)d_in[14];
    const float* fc_b      = (const float*)d_in[15];
    const int*   in_text   = (const int*)d_in[16];
    const int*   poses     = (const int*)d_in[18];
    float* out = (float*)d_out;

    cudaFuncSetAttribute(gk<0>,  cudaFuncAttributeMaxDynamicSharedMemorySize, SMTOT);
    cudaFuncSetAttribute(gk<1>,  cudaFuncAttributeMaxDynamicSharedMemorySize, SMTOT);
    cudaFuncSetAttribute(gk<4>,  cudaFuncAttributeMaxDynamicSharedMemorySize, SMTOT);
    cudaFuncSetAttribute(enc_run, cudaFuncAttributeMaxDynamicSharedMemorySize, SMTOT_E);
    cudaFuncSetAttribute(dec_run, cudaFuncAttributeMaxDynamicSharedMemorySize, SMTOT_D);

    prep_a<<<dim3(128,2),256>>>(enc_emb, dec_emb);
    prep_w<<<dim3(256,7),256>>>(enc_Wih_f, enc_bih_f, enc_Wih_b, enc_bih_b,
                                dec_Wih, dec_bih, enc_Whh_f, enc_bhh_f,
                                enc_Whh_b, enc_bhh_b, dec_Whh, dec_bhh, fc_W);
    init_h<<<(128*KP2+255)/256,256>>>();

    gk<0><<<dim3(32,31,2),256,SMTOT>>>(nullptr, nullptr);
    gk<1><<<dim3(32,5,1), 256,SMTOT>>>(nullptr, nullptr);

    enc_run<<<128,256,SMTOT_E>>>(in_text);
    combine<<<(128*HID+255)/256,256>>>();
    dec_run<<<128,256,SMTOT_D>>>(poses);

    gk<4><<<dim3(6,90,1),256,SMTOT>>>(fc_b, out);
}